// round 12
// baseline (speedup 1.0000x reference)
#include <cuda_runtime.h>

// Shapes (fixed):
//   image: (3, 512, 512) f32
//   x:     (16, 1, 512, 512) f32
//   W:     (9, 3, 3, 3) f32   b: (9,) f32
//   out:   (16, 1, 512, 512) f32
//
// Stage A: K[c,i,j] = b[c] + sum_{m,u,v} W[c,m,u,v]*image[m,i+u-1,j+v-1]
// Stage B: y[n,i,j] = sum_{u,v} x[n,i+u-1,j+v-1] * K[u*3+v,i,j]
// K (9 planes, 9.4 MB) is materialized in __device__ scratch (L2-resident).

#define HH 512
#define WW 512
#define NB 16
#define PLANE (HH * WW)
#define FULLMASK 0xffffffffu

__device__ float Kscratch[9 * PLANE];   // 9.4 MB static device scratch

// ---------------------------------------------------------------------------
// Kernel A: per-pixel 3x3 kernels from the 3->9 channel conv. 2 px/thread.
// (unchanged — measured ~3.4 us)
// ---------------------------------------------------------------------------
__global__ __launch_bounds__(128)
void kernelK(const float* __restrict__ image,
             const float* __restrict__ Wt,
             const float* __restrict__ bb)
{
    __shared__ __align__(16) float Wsh[9 * 28];
    __shared__ float bsh[9];

    const int tx = threadIdx.x;          // 0..127
    for (int idx = tx; idx < 243; idx += 128) {
        int c = idx / 27;
        int t = idx % 27;
        Wsh[c * 28 + t] = Wt[idx];
    }
    if (tx < 9) bsh[tx] = bb[tx];
    __syncthreads();

    const int col0 = blockIdx.x * 256 + tx * 2;   // 2 px per thread
    const int i    = blockIdx.y;                  // row 0..511

    const bool rok0 = (i > 0);
    const bool rok2 = (i < HH - 1);
    const bool lok  = (col0 > 0);
    const bool rtok = (col0 < WW - 2);

    float win[3][3][4];   // [m][row][col], cols col0-1..col0+2
    const float* base = image + (size_t)i * WW + col0;
    #pragma unroll
    for (int m = 0; m < 3; m++) {
        const float* bm = base + (size_t)m * PLANE;
        #pragma unroll
        for (int u = 0; u < 3; u++) {
            const float* p = bm + (u - 1) * WW;
            bool rowok = (u == 1) ? true : (u == 0 ? rok0 : rok2);
            float2 v = make_float2(0.f, 0.f);
            if (rowok) v = *(const float2*)p;
            win[m][u][1] = v.x;
            win[m][u][2] = v.y;
            win[m][u][0] = (rowok && lok)  ? p[-1] : 0.f;
            win[m][u][3] = (rowok && rtok) ? p[2]  : 0.f;
        }
    }

    float* kout = Kscratch + (size_t)i * WW + col0;
    #pragma unroll
    for (int c = 0; c < 9; c++) {
        float4 wa = *(const float4*)&Wsh[c * 28 + 0];
        float4 wb = *(const float4*)&Wsh[c * 28 + 4];
        float4 wc = *(const float4*)&Wsh[c * 28 + 8];
        float4 wd = *(const float4*)&Wsh[c * 28 + 12];
        float4 we = *(const float4*)&Wsh[c * 28 + 16];
        float4 wf = *(const float4*)&Wsh[c * 28 + 20];
        float4 wg = *(const float4*)&Wsh[c * 28 + 24];
        float wv[27] = {wa.x, wa.y, wa.z, wa.w, wb.x, wb.y, wb.z, wb.w,
                        wc.x, wc.y, wc.z, wc.w, wd.x, wd.y, wd.z, wd.w,
                        we.x, we.y, we.z, we.w, wf.x, wf.y, wf.z, wf.w,
                        wg.x, wg.y, wg.z};
        float k0 = bsh[c], k1 = bsh[c];
        #pragma unroll
        for (int m = 0; m < 3; m++) {
            #pragma unroll
            for (int u = 0; u < 3; u++) {
                #pragma unroll
                for (int v = 0; v < 3; v++) {
                    float w = wv[m * 9 + u * 3 + v];
                    k0 = fmaf(w, win[m][u][v + 0], k0);
                    k1 = fmaf(w, win[m][u][v + 1], k1);
                }
            }
        }
        *(float2*)(kout + (size_t)c * PLANE) = make_float2(k0, k1);
    }
}

// ---------------------------------------------------------------------------
// Kernel B: apply per-pixel kernels. 4 px/thread, block = full 512-px row,
// 8 slices/block. K streamed from SMEM (freed 36 regs -> 6 blocks/SM).
// 3 window buffers (float4 + 1 edge reg per row), prefetch distance 2.
// ---------------------------------------------------------------------------

struct Win {
    float4 v[3];   // rows u=0..2, cols col0..col0+3
    float  e[3];   // per-row edge value (lane0: p[-1], lane31: p[4])
};

__device__ __forceinline__ void load_win(const float* __restrict__ cb,
                                         bool rok0, bool rok2,
                                         bool eact, int eoff, Win& w)
{
    #pragma unroll
    for (int u = 0; u < 3; u++) {
        const float* p = cb + (u - 1) * WW;
        const bool rowok = (u == 1) ? true : (u == 0 ? rok0 : rok2);
        float4 v = make_float4(0.f, 0.f, 0.f, 0.f);
        if (rowok) v = *(const float4*)p;          // 16B aligned
        w.v[u] = v;
        float e = 0.f;
        if (eact && rowok) e = p[eoff];            // 2-active-lane LDG
        w.e[u] = e;
    }
}

__global__ __launch_bounds__(128, 6)
void kernelApply(const float* __restrict__ x,
                 float* __restrict__ y)
{
    __shared__ __align__(16) float Ksh[9 * 512];   // 18 KB: row's K tile

    const int tx   = threadIdx.x;              // 0..127, block = full row
    const int lane = tx & 31;
    const int col0 = tx * 4;                   // 4 px/thread, 16B aligned
    const int i    = blockIdx.y;               // row
    const int n0   = blockIdx.z * 8;           // 8 slices per block

    const bool rok0 = (i > 0);
    const bool rok2 = (i < HH - 1);
    const bool eact = (lane == 0 && tx != 0) || (lane == 31 && tx != 127);
    const int  eoff = (lane == 0) ? -1 : 4;

    const float* xb = x + (size_t)n0 * PLANE + (size_t)i * WW + col0;
    float*       yb = y + (size_t)n0 * PLANE + (size_t)i * WW + col0;

    // ---- preamble: x slices 0,1 launched FIRST (longest latency path) ----
    Win Xw[3];
    load_win(xb,         rok0, rok2, eact, eoff, Xw[0]);
    load_win(xb + PLANE, rok0, rok2, eact, eoff, Xw[1]);

    // ---- stage the row's K tile into smem (9x LDG.128 + 9x STS.128) ----
    {
        const float* kb = Kscratch + (size_t)i * WW + col0;
        #pragma unroll
        for (int c = 0; c < 9; c++) {
            float4 kv = *(const float4*)(kb + (size_t)c * PLANE);
            *(float4*)&Ksh[c * 512 + col0] = kv;
        }
    }
    __syncthreads();

    #pragma unroll
    for (int n = 0; n < 8; n++) {
        if (n + 2 < 8)   // prefetch distance 2
            load_win(xb + (size_t)(n + 2) * PLANE, rok0, rok2, eact, eoff,
                     Xw[(n + 2) % 3]);

        const Win& w = Xw[n % 3];
        float a0 = 0.f, a1 = 0.f, a2 = 0.f, a3 = 0.f;
        #pragma unroll
        for (int u = 0; u < 3; u++) {
            const float4 v = w.v[u];
            float sl = __shfl_up_sync(FULLMASK, v.w, 1);
            float sr = __shfl_down_sync(FULLMASK, v.x, 1);
            float r0 = (lane == 0)  ? w.e[u] : sl;
            float r5 = (lane == 31) ? w.e[u] : sr;
            float r[6] = {r0, v.x, v.y, v.z, v.w, r5};

            #pragma unroll
            for (int vv = 0; vv < 3; vv++) {
                const int c = u * 3 + vv;
                // stream K from smem: one LDS.128, values used once per slice
                float4 k4 = *(const float4*)&Ksh[c * 512 + col0];
                a0 = fmaf(r[vv + 0], k4.x, a0);
                a1 = fmaf(r[vv + 1], k4.y, a1);
                a2 = fmaf(r[vv + 2], k4.z, a2);
                a3 = fmaf(r[vv + 3], k4.w, a3);
            }
        }
        float4 o; o.x = a0; o.y = a1; o.z = a2; o.w = a3;
        *(float4*)(yb + (size_t)n * PLANE) = o;
    }
}

extern "C" void kernel_launch(void* const* d_in, const int* in_sizes, int n_in,
                              void* d_out, int out_size)
{
    const float* image = (const float*)d_in[0];   // 3*512*512
    const float* x     = (const float*)d_in[1];   // 16*512*512
    const float* Wt    = (const float*)d_in[2];   // 243
    const float* bb    = (const float*)d_in[3];   // 9
    float* y = (float*)d_out;                     // 16*512*512

    dim3 blockA(128);
    dim3 gridA(WW / 256, HH);        // (2, 512) = 1024 blocks
    kernelK<<<gridA, blockA>>>(image, Wt, bb);

    dim3 blockB(128);
    dim3 gridB(1, HH, NB / 8);       // (1, 512, 2) = 1024 blocks, 8 slices each
    kernelApply<<<gridB, blockB>>>(x, y);
}

// round 13
// speedup vs baseline: 1.2510x; 1.2510x over previous
#include <cuda_runtime.h>

// Shapes (fixed):
//   image: (3, 512, 512) f32
//   x:     (16, 1, 512, 512) f32
//   W:     (9, 3, 3, 3) f32   b: (9,) f32
//   out:   (16, 1, 512, 512) f32
//
// Stage A: K[c,i,j] = b[c] + sum_{m,u,v} W[c,m,u,v]*image[m,i+u-1,j+v-1]
// Stage B: y[n,i,j] = sum_{u,v} x[n,i+u-1,j+v-1] * K[u*3+v,i,j]
// K (9 planes, 9.4 MB) materialized in __device__ scratch (L2-resident).
// B is PDL-launched: it prefetches x (A-independent) before the grid
// dependency sync, overlapping A's tail + launch gap.

#define HH 512
#define WW 512
#define NB 16
#define PLANE (HH * WW)
#define FULLMASK 0xffffffffu

__device__ float Kscratch[9 * PLANE];   // 9.4 MB static device scratch

// ---------------------------------------------------------------------------
// Kernel A: per-pixel 3x3 kernels from the 3->9 channel conv. 2 px/thread.
// ---------------------------------------------------------------------------
__global__ __launch_bounds__(128)
void kernelK(const float* __restrict__ image,
             const float* __restrict__ Wt,
             const float* __restrict__ bb)
{
    __shared__ __align__(16) float Wsh[9 * 28];
    __shared__ float bsh[9];

    const int tx = threadIdx.x;          // 0..127
    for (int idx = tx; idx < 243; idx += 128) {
        int c = idx / 27;
        int t = idx % 27;
        Wsh[c * 28 + t] = Wt[idx];
    }
    if (tx < 9) bsh[tx] = bb[tx];
    __syncthreads();

    const int col0 = blockIdx.x * 256 + tx * 2;   // 2 px per thread
    const int i    = blockIdx.y;                  // row 0..511

    const bool rok0 = (i > 0);
    const bool rok2 = (i < HH - 1);
    const bool lok  = (col0 > 0);
    const bool rtok = (col0 < WW - 2);

    float win[3][3][4];   // [m][row][col], cols col0-1..col0+2
    const float* base = image + (size_t)i * WW + col0;
    #pragma unroll
    for (int m = 0; m < 3; m++) {
        const float* bm = base + (size_t)m * PLANE;
        #pragma unroll
        for (int u = 0; u < 3; u++) {
            const float* p = bm + (u - 1) * WW;
            bool rowok = (u == 1) ? true : (u == 0 ? rok0 : rok2);
            float2 v = make_float2(0.f, 0.f);
            if (rowok) v = *(const float2*)p;
            win[m][u][1] = v.x;
            win[m][u][2] = v.y;
            win[m][u][0] = (rowok && lok)  ? p[-1] : 0.f;
            win[m][u][3] = (rowok && rtok) ? p[2]  : 0.f;
        }
    }

    float* kout = Kscratch + (size_t)i * WW + col0;
    #pragma unroll
    for (int c = 0; c < 9; c++) {
        float4 wa = *(const float4*)&Wsh[c * 28 + 0];
        float4 wb = *(const float4*)&Wsh[c * 28 + 4];
        float4 wc = *(const float4*)&Wsh[c * 28 + 8];
        float4 wd = *(const float4*)&Wsh[c * 28 + 12];
        float4 we = *(const float4*)&Wsh[c * 28 + 16];
        float4 wf = *(const float4*)&Wsh[c * 28 + 20];
        float4 wg = *(const float4*)&Wsh[c * 28 + 24];
        float wv[27] = {wa.x, wa.y, wa.z, wa.w, wb.x, wb.y, wb.z, wb.w,
                        wc.x, wc.y, wc.z, wc.w, wd.x, wd.y, wd.z, wd.w,
                        we.x, we.y, we.z, we.w, wf.x, wf.y, wf.z, wf.w,
                        wg.x, wg.y, wg.z};
        float k0 = bsh[c], k1 = bsh[c];
        #pragma unroll
        for (int m = 0; m < 3; m++) {
            #pragma unroll
            for (int u = 0; u < 3; u++) {
                #pragma unroll
                for (int v = 0; v < 3; v++) {
                    float w = wv[m * 9 + u * 3 + v];
                    k0 = fmaf(w, win[m][u][v + 0], k0);
                    k1 = fmaf(w, win[m][u][v + 1], k1);
                }
            }
        }
        *(float2*)(kout + (size_t)c * PLANE) = make_float2(k0, k1);
    }

    // All of this thread's K stores are issued: allow dependent launch.
    cudaTriggerProgrammaticLaunchCompletion();
}

// ---------------------------------------------------------------------------
// Kernel B: 4 px/thread, block = full row, 8 slices/block.
// K in registers (loads right after grid-dep sync), 3 window buffers with
// PREFETCHED edges (float4 + 1 edge reg/row), prefetch distance 2.
// ---------------------------------------------------------------------------

struct Win {
    float4 v[3];   // rows u=0..2, cols col0..col0+3
    float  e[3];   // per-row edge value (lane0: p[-1], lane31: p[4])
};

__device__ __forceinline__ void load_win(const float* __restrict__ cb,
                                         bool rok0, bool rok2,
                                         bool eact, int eoff, Win& w)
{
    #pragma unroll
    for (int u = 0; u < 3; u++) {
        const float* p = cb + (u - 1) * WW;
        const bool rowok = (u == 1) ? true : (u == 0 ? rok0 : rok2);
        float4 v = make_float4(0.f, 0.f, 0.f, 0.f);
        if (rowok) v = *(const float4*)p;          // 16B aligned
        w.v[u] = v;
        float e = 0.f;
        if (eact && rowok) e = p[eoff];            // one 2-active-lane LDG
        w.e[u] = e;
    }
}

__global__ __launch_bounds__(128, 5)
void kernelApply(const float* __restrict__ x,
                 float* __restrict__ y)
{
    const int tx   = threadIdx.x;              // 0..127, block = full row
    const int lane = tx & 31;
    const int col0 = tx * 4;                   // 4 px/thread, 16B aligned
    const int i    = blockIdx.y;               // row
    const int n0   = blockIdx.z * 8;           // 8 slices per block

    const bool rok0 = (i > 0);
    const bool rok2 = (i < HH - 1);
    const bool eact = (lane == 0 && tx != 0) || (lane == 31 && tx != 127);
    const int  eoff = (lane == 0) ? -1 : 4;

    const float* xb = x + (size_t)n0 * PLANE + (size_t)i * WW + col0;
    float*       yb = y + (size_t)n0 * PLANE + (size_t)i * WW + col0;

    // ---- x prefetches FIRST: independent of kernel A, overlap its tail ----
    Win Xw[3];
    load_win(xb,         rok0, rok2, eact, eoff, Xw[0]);
    load_win(xb + PLANE, rok0, rok2, eact, eoff, Xw[1]);

    // ---- wait for A's K stores, then load K into registers ----
    cudaGridDependencySynchronize();

    float K[36];   // K[c*4 + p]
    {
        const float* kb = Kscratch + (size_t)i * WW + col0;
        #pragma unroll
        for (int c = 0; c < 9; c++) {
            float4 kv = *(const float4*)(kb + (size_t)c * PLANE);
            K[c * 4 + 0] = kv.x; K[c * 4 + 1] = kv.y;
            K[c * 4 + 2] = kv.z; K[c * 4 + 3] = kv.w;
        }
    }

    #pragma unroll
    for (int n = 0; n < 8; n++) {
        if (n + 2 < 8)   // prefetch distance 2
            load_win(xb + (size_t)(n + 2) * PLANE, rok0, rok2, eact, eoff,
                     Xw[(n + 2) % 3]);

        const Win& w = Xw[n % 3];
        float a0 = 0.f, a1 = 0.f, a2 = 0.f, a3 = 0.f;
        #pragma unroll
        for (int u = 0; u < 3; u++) {
            const float4 v = w.v[u];
            float sl = __shfl_up_sync(FULLMASK, v.w, 1);
            float sr = __shfl_down_sync(FULLMASK, v.x, 1);
            float r0 = (lane == 0)  ? w.e[u] : sl;
            float r5 = (lane == 31) ? w.e[u] : sr;
            float r[6] = {r0, v.x, v.y, v.z, v.w, r5};

            #pragma unroll
            for (int vv = 0; vv < 3; vv++) {
                const int c = u * 3 + vv;
                a0 = fmaf(r[vv + 0], K[c * 4 + 0], a0);
                a1 = fmaf(r[vv + 1], K[c * 4 + 1], a1);
                a2 = fmaf(r[vv + 2], K[c * 4 + 2], a2);
                a3 = fmaf(r[vv + 3], K[c * 4 + 3], a3);
            }
        }
        float4 o; o.x = a0; o.y = a1; o.z = a2; o.w = a3;
        *(float4*)(yb + (size_t)n * PLANE) = o;
    }
}

extern "C" void kernel_launch(void* const* d_in, const int* in_sizes, int n_in,
                              void* d_out, int out_size)
{
    const float* image = (const float*)d_in[0];   // 3*512*512
    const float* x     = (const float*)d_in[1];   // 16*512*512
    const float* Wt    = (const float*)d_in[2];   // 243
    const float* bb    = (const float*)d_in[3];   // 9
    float* y = (float*)d_out;                     // 16*512*512

    dim3 blockA(128);
    dim3 gridA(WW / 256, HH);        // (2, 512) = 1024 blocks
    kernelK<<<gridA, blockA>>>(image, Wt, bb);

    // PDL launch for B: may start while A drains; B syncs before reading K.
    cudaLaunchConfig_t cfg = {};
    cfg.gridDim  = dim3(1, HH, NB / 8);   // (1, 512, 2) = 1024 blocks
    cfg.blockDim = dim3(128);
    cudaLaunchAttribute attr[1];
    attr[0].id = cudaLaunchAttributeProgrammaticStreamSerialization;
    attr[0].val.programmaticStreamSerializationAllowed = 1;
    cfg.attrs    = attr;
    cfg.numAttrs = 1;
    cudaLaunchKernelEx(&cfg, kernelApply, x, y);
}